// round 7
// baseline (speedup 1.0000x reference)
#include <cuda_runtime.h>
#include <cuda_bf16.h>

#define BATCH 32
#define SEQ   4096
#define EMBED 512
#define HID   256
#define OUTD  128
#define DECAYF 0.95f

__device__ float    g_xm[SEQ * EMBED];    // batch-mean [4096][512]
__device__ float    g_curT[HID * SEQ];    // currents TRANSPOSED [256][4096]
__device__ float    g_cnt[HID];           // spike counts
__device__ unsigned g_done;               // last-block flag (self-resetting)

// ---------------------------------------------------------------------------
// Kernel 1: batch mean over B=32 (82% of HBM — keep).
// ---------------------------------------------------------------------------
__global__ void snn_mean_kernel(const float* __restrict__ x) {
    const int NF4 = (SEQ * EMBED) / 4;
    int i = blockIdx.x * blockDim.x + threadIdx.x;
    if (i >= NF4) return;
    const float4* x4 = reinterpret_cast<const float4*>(x);
    float sx = 0.f, sy = 0.f, sz = 0.f, sw = 0.f;
#pragma unroll
    for (int b = 0; b < BATCH; b++) {
        float4 v = x4[(size_t)b * NF4 + i];
        sx += v.x; sy += v.y; sz += v.z; sw += v.w;
    }
    const float inv = 1.0f / 32.0f;
    float4 r; r.x = sx * inv; r.y = sy * inv; r.z = sz * inv; r.w = sw * inv;
    reinterpret_cast<float4*>(g_xm)[i] = r;
}

// ---------------------------------------------------------------------------
// Kernel 2: SGEMM currents^T = (xm @ W1)^T.  (R5 exact — 128 threads,
// 64x128 tile, 8x8 micro, n-packed f32x2, cp.async double-buffered.)
// ---------------------------------------------------------------------------
#define GBM 64
#define GBN 128
#define GBK 32
#define APITCH 36
#define SA_SZ (GBM * APITCH)
#define SB_SZ (GBK * GBN)
#define GEMM_SMEM_BYTES (12800 * 4)

typedef unsigned long long ull;

__device__ __forceinline__ void fma2(ull& d, ull a, ull b) {
    asm("fma.rn.f32x2 %0, %1, %2, %0;" : "+l"(d) : "l"(a), "l"(b));
}
__device__ __forceinline__ ull dup2(float a) {
    ull r;
    asm("mov.b64 %0, {%1, %1};" : "=l"(r) : "f"(a));
    return r;
}
__device__ __forceinline__ void cp16(unsigned dst, const void* src) {
    asm volatile("cp.async.cg.shared.global [%0], [%1], 16;" :: "r"(dst), "l"(src));
}
__device__ __forceinline__ void cp_commit() {
    asm volatile("cp.async.commit_group;");
}
__device__ __forceinline__ void cp_wait0() {
    asm volatile("cp.async.wait_group 0;");
}

__global__ void __launch_bounds__(128, 1)
snn_gemm_kernel(const float* __restrict__ W1) {
    extern __shared__ float gsm[];
    const unsigned smem_u32 = (unsigned)__cvta_generic_to_shared(gsm);

    const int tid = threadIdx.x;
    const int h0  = blockIdx.x * GBN;
    const int s0  = blockIdx.y * GBM;
    const int mgrp = tid >> 4;
    const int ngrp = tid & 15;
    const int m0 = mgrp * 8;
    const int n0 = ngrp * 8;

    auto load_chunk = [&](int c, int buf) {
        const int k0 = c * GBK;
        unsigned dA = smem_u32 + (buf * SA_SZ) * 4;
#pragma unroll
        for (int l = 0; l < 4; l++) {
            int f   = tid + l * 128;
            int row = f >> 3;
            int seg = f & 7;
            cp16(dA + (row * APITCH + seg * 4) * 4,
                 &g_xm[(size_t)(s0 + row) * EMBED + k0 + seg * 4]);
        }
        unsigned dB = smem_u32 + (4608 + buf * SB_SZ) * 4;
#pragma unroll
        for (int l = 0; l < 8; l++) {
            int f   = tid + l * 128;
            int row = f >> 5;
            int seg = f & 31;
            cp16(dB + (row * GBN + seg * 4) * 4,
                 &W1[(size_t)(k0 + row) * HID + h0 + seg * 4]);
        }
        cp_commit();
    };

    ull acc[8][4];
#pragma unroll
    for (int j = 0; j < 8; j++)
#pragma unroll
        for (int p = 0; p < 4; p++) acc[j][p] = 0ull;

    load_chunk(0, 0);

    const int NCHUNK = EMBED / GBK;
#pragma unroll 1
    for (int c = 0; c < NCHUNK; c++) {
        cp_wait0();
        __syncthreads();
        if (c + 1 < NCHUNK) load_chunk(c + 1, (c + 1) & 1);

        const float* pA = gsm + (c & 1) * SA_SZ + m0 * APITCH;
        const float* pB = gsm + 4608 + (c & 1) * SB_SZ + n0;
#pragma unroll 4
        for (int k = 0; k < GBK; k++) {
            ulonglong2 b01 = *reinterpret_cast<const ulonglong2*>(pB + k * GBN);
            ulonglong2 b23 = *reinterpret_cast<const ulonglong2*>(pB + k * GBN + 4);
#pragma unroll
            for (int j = 0; j < 8; j++) {
                ull ad = dup2(pA[j * APITCH + k]);
                fma2(acc[j][0], ad, b01.x);
                fma2(acc[j][1], ad, b01.y);
                fma2(acc[j][2], ad, b23.x);
                fma2(acc[j][3], ad, b23.y);
            }
        }
        __syncthreads();
    }

    float* sT = gsm;
#pragma unroll
    for (int j = 0; j < 8; j++) {
#pragma unroll
        for (int p = 0; p < 4; p++) {
            float2 v = *reinterpret_cast<float2*>(&acc[j][p]);
            sT[(n0 + 2 * p + 0) * 68 + (m0 + j)] = v.x;
            sT[(n0 + 2 * p + 1) * 68 + (m0 + j)] = v.y;
        }
    }
    __syncthreads();
#pragma unroll
    for (int l = 0; l < 16; l++) {
        int f    = tid + l * 128;
        int hrow = f >> 4;
        int seg  = f & 15;
        float4 v = *reinterpret_cast<float4*>(&sT[hrow * 68 + seg * 4]);
        *reinterpret_cast<float4*>(
            &g_curT[(size_t)(h0 + hrow) * SEQ + s0 + seg * 4]) = v;
    }
}

// ---------------------------------------------------------------------------
// Kernel 3: epoch-parallel LIF scan (R2 algorithm) + fused output.
// One block per hidden unit h, 1024 threads.
//   1) next-spike table: from each start a (mem=0), average epoch ~6 steps
//   2) pointer-doubling over packed (count<<13 | jump)
//   3) last finishing block computes out = cnt @ W2 / SEQ.
// ---------------------------------------------------------------------------
__global__ void __launch_bounds__(1024, 1)
snn_table_out_kernel(const float* __restrict__ W2, float* __restrict__ out) {
    __shared__ float    sc[SEQ + 4];
    __shared__ unsigned Pa[SEQ + 1];
    __shared__ unsigned slast;

    const int h   = blockIdx.x;
    const int tid = threadIdx.x;

    reinterpret_cast<float4*>(sc)[tid] =
        reinterpret_cast<const float4*>(&g_curT[(size_t)h * SEQ])[tid];
    __syncthreads();

    // Phase 1: next-spike per start (avg epoch ~6 steps)
#pragma unroll
    for (int r = 0; r < 4; r++) {
        int a = tid + r * 1024;
        float m = 0.f;
        int t = a;
        while (t < SEQ) {
            m = fmaf(DECAYF, m, sc[t]);
            if (m >= 1.0f) break;
            t++;
        }
        unsigned pk;
        if (t < SEQ) {
            int j = t + 3; if (j > SEQ) j = SEQ;
            pk = (1u << 13) | (unsigned)j;
        } else pk = (unsigned)SEQ;
        Pa[a] = pk;
    }
    if (tid == 0) Pa[SEQ] = (unsigned)SEQ;
    __syncthreads();

    // Phase 2: pointer doubling (12 rounds; chain <= 1366)
    unsigned* Pb   = reinterpret_cast<unsigned*>(sc);
    unsigned* srcp = Pa;
    unsigned* dstp = Pb;
#pragma unroll 1
    for (int r = 0; r < 12; r++) {
        for (int a = tid; a <= SEQ; a += 1024) {
            unsigned p = srcp[a];
            unsigned q = srcp[p & 8191u];
            dstp[a] = ((p & ~8191u) + (q & ~8191u)) | (q & 8191u);
        }
        __syncthreads();
        unsigned* tmp = srcp; srcp = dstp; dstp = tmp;
    }
    if (tid == 0) g_cnt[h] = (float)(srcp[0] >> 13);

    // Fused output: last block of 256 projects counts through W2.
    __syncthreads();
    __threadfence();
    if (tid == 0) slast = atomicAdd(&g_done, 1u);
    __syncthreads();

    if (slast == HID - 1 && tid < OUTD) {
        __threadfence();
        volatile float* vc = g_cnt;
        float a = 0.f;
#pragma unroll 16
        for (int k = 0; k < HID; k++)
            a += vc[k] * W2[(size_t)k * OUTD + tid];
        a *= (1.0f / (float)SEQ);
#pragma unroll
        for (int b = 0; b < BATCH; b++)
            out[(size_t)b * OUTD + tid] = a;
        __threadfence();
        if (tid == 0) g_done = 0;              // reset for next replay
    }
}

// ---------------------------------------------------------------------------
extern "C" void kernel_launch(void* const* d_in, const int* in_sizes, int n_in,
                              void* d_out, int out_size) {
    const float* x  = (const float*)d_in[0];   // [32][4096][512]
    const float* w1 = (const float*)d_in[1];   // [512][256]
    const float* w2 = (const float*)d_in[2];   // [256][128]
    float* out = (float*)d_out;                // [32][128]

    cudaFuncSetAttribute(snn_gemm_kernel,
                         cudaFuncAttributeMaxDynamicSharedMemorySize,
                         GEMM_SMEM_BYTES);

    snn_mean_kernel<<<(SEQ * EMBED / 4 + 255) / 256, 256>>>(x);
    snn_gemm_kernel<<<dim3(HID / GBN, SEQ / GBM), 128, GEMM_SMEM_BYTES>>>(w1);
    snn_table_out_kernel<<<HID, 1024>>>(w2, out);
}

// round 8
// speedup vs baseline: 1.2961x; 1.2961x over previous
#include <cuda_runtime.h>
#include <cuda_bf16.h>

#define BATCH 32
#define SEQ   4096
#define EMBED 512
#define HID   256
#define OUTD  128
#define DECAYF 0.95f
#define LOG2_INV_D 0.07400058144377693f   // log2(1/0.95)

__device__ float    g_xm[SEQ * EMBED];    // batch-mean [4096][512]
__device__ float    g_curT[HID * SEQ];    // currents TRANSPOSED [256][4096]
__device__ float    g_cnt[HID];           // spike counts
__device__ unsigned g_done;               // last-block flag (self-resetting)

// ---------------------------------------------------------------------------
// Kernel 1: batch mean over B=32 (83% of HBM — keep).
// ---------------------------------------------------------------------------
__global__ void snn_mean_kernel(const float* __restrict__ x) {
    const int NF4 = (SEQ * EMBED) / 4;
    int i = blockIdx.x * blockDim.x + threadIdx.x;
    if (i >= NF4) return;
    const float4* x4 = reinterpret_cast<const float4*>(x);
    float sx = 0.f, sy = 0.f, sz = 0.f, sw = 0.f;
#pragma unroll
    for (int b = 0; b < BATCH; b++) {
        float4 v = x4[(size_t)b * NF4 + i];
        sx += v.x; sy += v.y; sz += v.z; sw += v.w;
    }
    const float inv = 1.0f / 32.0f;
    float4 r; r.x = sx * inv; r.y = sy * inv; r.z = sz * inv; r.w = sw * inv;
    reinterpret_cast<float4*>(g_xm)[i] = r;
}

// ---------------------------------------------------------------------------
// Kernel 2 (v2): SGEMM currents^T = (xm @ W1)^T.
// 64(s) x 64(h) tile, grid (4,64)=256 blocks, 256 threads (2 blocks/SM,
// 4 warps/SMSP), micro 4s x 4h, n-packed f32x2, cp.async double-buffered.
// ---------------------------------------------------------------------------
#define GBM 64
#define GBN 64
#define GBK 32
#define APITCH 36                 // A row pitch (floats)
#define BPITCH 68                 // B row pitch (floats)
#define SA_SZ (GBM * APITCH)      // 2304 floats
#define SB_SZ (GBK * BPITCH)      // 2176 floats
// layout: sA0 @0, sA1 @2304, sB0 @4608, sB1 @6784; epilogue sT reuses base
#define GEMM_SMEM_FLOATS (4608 + 2 * SB_SZ)   // 8960 floats = 35840 B
#define GEMM_SMEM_BYTES  (GEMM_SMEM_FLOATS * 4)

typedef unsigned long long ull;

__device__ __forceinline__ void fma2(ull& d, ull a, ull b) {
    asm("fma.rn.f32x2 %0, %1, %2, %0;" : "+l"(d) : "l"(a), "l"(b));
}
__device__ __forceinline__ ull dup2(float a) {
    ull r;
    asm("mov.b64 %0, {%1, %1};" : "=l"(r) : "f"(a));
    return r;
}
__device__ __forceinline__ void cp16(unsigned dst, const void* src) {
    asm volatile("cp.async.cg.shared.global [%0], [%1], 16;" :: "r"(dst), "l"(src));
}
__device__ __forceinline__ void cp_commit() {
    asm volatile("cp.async.commit_group;");
}
__device__ __forceinline__ void cp_wait0() {
    asm volatile("cp.async.wait_group 0;");
}

__global__ void __launch_bounds__(256, 2)
snn_gemm_kernel(const float* __restrict__ W1) {
    extern __shared__ float gsm[];
    const unsigned smem_u32 = (unsigned)__cvta_generic_to_shared(gsm);

    const int tid = threadIdx.x;
    const int h0  = blockIdx.x * GBN;
    const int s0  = blockIdx.y * GBM;
    const int mgrp = tid >> 4;       // 0..15 -> 4 s-rows each
    const int ngrp = tid & 15;       // 0..15 -> 4 h-cols each
    const int m0 = mgrp * 4;
    const int n0 = ngrp * 4;

    auto load_chunk = [&](int c, int buf) {
        const int k0 = c * GBK;
        // A: 64 rows x 32 k = 512 f4, 2 per thread
        unsigned dA = smem_u32 + (buf * SA_SZ) * 4;
#pragma unroll
        for (int l = 0; l < 2; l++) {
            int f   = tid + l * 256;      // 0..511
            int row = f >> 3;
            int seg = f & 7;
            cp16(dA + (row * APITCH + seg * 4) * 4,
                 &g_xm[(size_t)(s0 + row) * EMBED + k0 + seg * 4]);
        }
        // B: 32 k x 64 h = 512 f4, 2 per thread
        unsigned dB = smem_u32 + (4608 + buf * SB_SZ) * 4;
#pragma unroll
        for (int l = 0; l < 2; l++) {
            int f   = tid + l * 256;      // 0..511
            int row = f >> 4;             // k row 0..31
            int seg = f & 15;             // h f4-seg 0..15
            cp16(dB + (row * BPITCH + seg * 4) * 4,
                 &W1[(size_t)(k0 + row) * HID + h0 + seg * 4]);
        }
        cp_commit();
    };

    ull acc[4][2];
#pragma unroll
    for (int j = 0; j < 4; j++) { acc[j][0] = 0ull; acc[j][1] = 0ull; }

    load_chunk(0, 0);

    const int NCHUNK = EMBED / GBK;   // 16
#pragma unroll 1
    for (int c = 0; c < NCHUNK; c++) {
        cp_wait0();
        __syncthreads();
        if (c + 1 < NCHUNK) load_chunk(c + 1, (c + 1) & 1);

        const float* pA = gsm + (c & 1) * SA_SZ + m0 * APITCH;
        const float* pB = gsm + 4608 + (c & 1) * SB_SZ + n0;
#pragma unroll 8
        for (int k = 0; k < GBK; k++) {
            ulonglong2 b01 = *reinterpret_cast<const ulonglong2*>(pB + k * BPITCH);
#pragma unroll
            for (int j = 0; j < 4; j++) {
                ull ad = dup2(pA[j * APITCH + k]);
                fma2(acc[j][0], ad, b01.x);
                fma2(acc[j][1], ad, b01.y);
            }
        }
        __syncthreads();
    }

    // epilogue: stage transposed [h][s] tile, coalesced f4 stores
    float* sT = gsm;                  // [64][68] = 4352 floats
#pragma unroll
    for (int j = 0; j < 4; j++) {
#pragma unroll
        for (int p = 0; p < 2; p++) {
            float2 v = *reinterpret_cast<float2*>(&acc[j][p]);
            sT[(n0 + 2 * p + 0) * 68 + (m0 + j)] = v.x;
            sT[(n0 + 2 * p + 1) * 68 + (m0 + j)] = v.y;
        }
    }
    __syncthreads();
#pragma unroll
    for (int l = 0; l < 4; l++) {
        int f    = tid + l * 256;     // 0..1023
        int hrow = f >> 4;            // 0..63
        int seg  = f & 15;            // s f4-seg
        float4 v = *reinterpret_cast<float4*>(&sT[hrow * 68 + seg * 4]);
        *reinterpret_cast<float4*>(
            &g_curT[(size_t)(h0 + hrow) * SEQ + s0 + seg * 4]) = v;
    }
}

// ---------------------------------------------------------------------------
// Kernel 3: warp-window LIF scan (R5 exact) + fused output projection.
// 64 blocks x 128 threads; warp w handles unit h = 4*blockIdx + w.
// ---------------------------------------------------------------------------
__global__ void __launch_bounds__(128, 1)
snn_table_out_kernel(const float* __restrict__ W2, float* __restrict__ out) {
    extern __shared__ float scs[];    // 4 rows x 4096 floats = 64 KB
    __shared__ unsigned slast;

    const int tid  = threadIdx.x;
    const int lane = tid & 31;
    const int w    = tid >> 5;
    const int hbase = blockIdx.x * 4;

    const float4* src = reinterpret_cast<const float4*>(&g_curT[(size_t)hbase * SEQ]);
#pragma unroll
    for (int l = 0; l < 32; l++)
        reinterpret_cast<float4*>(scs)[tid + l * 128] = src[tid + l * 128];
    __syncthreads();

    const float dinv = exp2f((float)lane * LOG2_INV_D);   // d^{-lane}
    const float d31  = exp2f(-31.0f * LOG2_INV_D);        // d^31

    const float* row = &scs[w * SEQ];
    float X = 0.f;
    int   o = 0;
    int   carry_bnd = 0, carry_o = 0;
    int   cnt = 0;

#pragma unroll 1
    for (int win = 0; win < SEQ / 32; win++) {
        float c = row[win * 32 + lane];
        float p = c * dinv;
#pragma unroll
        for (int off = 1; off < 32; off <<= 1) {
            float v = __shfl_up_sync(0xffffffffu, p, off);
            if (lane >= off) p += v;
        }
        const float Q   = p - dinv;
        const float P31 = __shfl_sync(0xffffffffu, p, 31);

        if (carry_bnd) {
            o = carry_o;
            X = (carry_o == 0) ? 0.f : __shfl_sync(0xffffffffu, p, carry_o - 1);
            carry_bnd = 0;
        }

        for (;;) {
            unsigned mask = __ballot_sync(0xffffffffu, (Q >= X) && (lane >= o));
            if (!mask) {
                float m31 = d31 * (P31 - X);
                X = -DECAYF * m31;
                o = 0;
                break;
            }
            int ts = __ffs(mask) - 1;
            cnt++;
            if (ts >= 29) {
                carry_bnd = 1;
                carry_o = ts - 29;
                break;
            }
            o = ts + 3;
            X = __shfl_sync(0xffffffffu, p, ts + 2);
        }
    }

    if (lane == 0) g_cnt[hbase + w] = (float)cnt;
    __syncthreads();
    __threadfence();
    if (tid == 0) slast = atomicAdd(&g_done, 1u);
    __syncthreads();

    if (slast == 63) {
        __threadfence();
        volatile float* vc = g_cnt;
        float a = 0.f;
#pragma unroll 16
        for (int k = 0; k < HID; k++)
            a += vc[k] * W2[(size_t)k * OUTD + tid];
        a *= (1.0f / (float)SEQ);
#pragma unroll
        for (int b = 0; b < BATCH; b++)
            out[(size_t)b * OUTD + tid] = a;
        __threadfence();
        if (tid == 0) g_done = 0;
    }
}

// ---------------------------------------------------------------------------
extern "C" void kernel_launch(void* const* d_in, const int* in_sizes, int n_in,
                              void* d_out, int out_size) {
    const float* x  = (const float*)d_in[0];   // [32][4096][512]
    const float* w1 = (const float*)d_in[1];   // [512][256]
    const float* w2 = (const float*)d_in[2];   // [256][128]
    float* out = (float*)d_out;                // [32][128]

    cudaFuncSetAttribute(snn_gemm_kernel,
                         cudaFuncAttributeMaxDynamicSharedMemorySize,
                         GEMM_SMEM_BYTES);
    cudaFuncSetAttribute(snn_table_out_kernel,
                         cudaFuncAttributeMaxDynamicSharedMemorySize,
                         4 * SEQ * (int)sizeof(float));

    snn_mean_kernel<<<(SEQ * EMBED / 4 + 255) / 256, 256>>>(x);
    snn_gemm_kernel<<<dim3(HID / GBN, SEQ / GBM), 256, GEMM_SMEM_BYTES>>>(w1);
    snn_table_out_kernel<<<HID / 4, 128, 4 * SEQ * sizeof(float)>>>(w2, out);
}

// round 10
// speedup vs baseline: 1.3109x; 1.0114x over previous
#include <cuda_runtime.h>
#include <cuda_bf16.h>
#include <cstdint>

#define BATCH 32
#define SEQ   4096
#define EMBED 512
#define HID   256
#define OUTD  128
#define DECAYF 0.95f
#define LOG2_INV_D 0.07400058144377693f   // log2(1/0.95)

#define KSPLIT (3 * EMBED)                // 1536: A = (hi | hi | lo)

__device__ __nv_bfloat16 g_a3[SEQ * KSPLIT];    // A split   [4096][1536]
__device__ __nv_bfloat16 g_w1t[HID * KSPLIT];   // W1^T split [256][1536]: (hi|lo|hi)
__device__ float    g_curT[HID * SEQ];          // currents TRANSPOSED [256][4096]
__device__ float    g_cnt[HID];
__device__ unsigned g_done;

// ---------------------------------------------------------------------------
// Kernel 0: W1 split prep: g_w1t[n][k]=hi, [n][512+k]=lo, [n][1024+k]=hi.
// ---------------------------------------------------------------------------
__global__ void snn_wprep_kernel(const float* __restrict__ W1) {
    const int k = blockIdx.x;        // 512
    const int n = threadIdx.x;       // 256
    float v = W1[(size_t)k * HID + n];
    __nv_bfloat16 hi = __float2bfloat16(v);
    __nv_bfloat16 lo = __float2bfloat16(v - __bfloat162float(hi));
    g_w1t[(size_t)n * KSPLIT + k]              = hi;
    g_w1t[(size_t)n * KSPLIT + EMBED + k]      = lo;
    g_w1t[(size_t)n * KSPLIT + 2 * EMBED + k]  = hi;
}

// ---------------------------------------------------------------------------
// Kernel 1: batch mean, emits split-bf16 A3 (hi | hi | lo).
// ---------------------------------------------------------------------------
__global__ void snn_mean_kernel(const float* __restrict__ x) {
    const int NF4 = (SEQ * EMBED) / 4;
    int i = blockIdx.x * blockDim.x + threadIdx.x;
    if (i >= NF4) return;
    const float4* x4 = reinterpret_cast<const float4*>(x);
    float sx = 0.f, sy = 0.f, sz = 0.f, sw = 0.f;
#pragma unroll
    for (int b = 0; b < BATCH; b++) {
        float4 v = x4[(size_t)b * NF4 + i];
        sx += v.x; sy += v.y; sz += v.z; sw += v.w;
    }
    const float inv = 1.0f / 32.0f;
    float v0 = sx * inv, v1 = sy * inv, v2 = sz * inv, v3 = sw * inv;

    __nv_bfloat16 h0 = __float2bfloat16(v0), h1 = __float2bfloat16(v1);
    __nv_bfloat16 h2 = __float2bfloat16(v2), h3 = __float2bfloat16(v3);
    __nv_bfloat16 l0 = __float2bfloat16(v0 - __bfloat162float(h0));
    __nv_bfloat16 l1 = __float2bfloat16(v1 - __bfloat162float(h1));
    __nv_bfloat16 l2 = __float2bfloat16(v2 - __bfloat162float(h2));
    __nv_bfloat16 l3 = __float2bfloat16(v3 - __bfloat162float(h3));

    __nv_bfloat162 ha = {h0, h1}, hb = {h2, h3};
    __nv_bfloat162 la = {l0, l1}, lb = {l2, l3};
    uint2 hu, lu;
    hu.x = *reinterpret_cast<unsigned*>(&ha); hu.y = *reinterpret_cast<unsigned*>(&hb);
    lu.x = *reinterpret_cast<unsigned*>(&la); lu.y = *reinterpret_cast<unsigned*>(&lb);

    const int s = i >> 7, d4 = i & 127;
    const size_t base = (size_t)s * KSPLIT + d4 * 4;
    *reinterpret_cast<uint2*>(&g_a3[base])             = hu;
    *reinterpret_cast<uint2*>(&g_a3[base + EMBED])     = hu;
    *reinterpret_cast<uint2*>(&g_a3[base + 2 * EMBED]) = lu;
}

// ---------------------------------------------------------------------------
// Kernel 2: HMMA bf16 GEMM via mma.sync.m16n8k16 (portable, no tcgen05).
// Block tile 128(s) x 64(h), K'=1536, BK=64 double-buffered cp.async.
// 8 warps = 4(m) x 2(n); warp tile 32x32. Grid (32, 4), 256 threads.
// ---------------------------------------------------------------------------
#define MT 128
#define NT 64
#define KCH 64
#define NCH (KSPLIT / KCH)        // 24
#define APIT 72                   // smem pitch (bf16) for A/B: conflict-free frags
#define SA_BYTES (MT * APIT * 2)  // 18432
#define SB_BYTES (NT * APIT * 2)  // 9216
// layout (bytes): A0 @0, A1 @18432, B0 @36864, B1 @46080; total 55296
#define SMB_OFF 36864
#define MMA_SMEM_BYTES 55296

__device__ __forceinline__ void cp16(unsigned dst, const void* src) {
    asm volatile("cp.async.cg.shared.global [%0], [%1], 16;" :: "r"(dst), "l"(src));
}
#define CP_COMMIT() asm volatile("cp.async.commit_group;")
#define CP_WAIT0()  asm volatile("cp.async.wait_group 0;")

__device__ __forceinline__ void mma16816(float& d0, float& d1, float& d2, float& d3,
                                         uint32_t a0, uint32_t a1, uint32_t a2, uint32_t a3,
                                         uint32_t b0, uint32_t b1) {
    asm volatile(
        "mma.sync.aligned.m16n8k16.row.col.f32.bf16.bf16.f32 "
        "{%0,%1,%2,%3}, {%4,%5,%6,%7}, {%8,%9}, {%0,%1,%2,%3};"
        : "+f"(d0), "+f"(d1), "+f"(d2), "+f"(d3)
        : "r"(a0), "r"(a1), "r"(a2), "r"(a3), "r"(b0), "r"(b1));
}

__global__ void __launch_bounds__(256, 1)
snn_mma_kernel(void) {
    extern __shared__ char smem[];
    const unsigned sb = (unsigned)__cvta_generic_to_shared(smem);
    __nv_bfloat16* sm16 = reinterpret_cast<__nv_bfloat16*>(smem);

    const int tid  = threadIdx.x;
    const int wid  = tid >> 5;
    const int lane = tid & 31;
    const int g = lane >> 2;         // 0..7
    const int t = lane & 3;          // 0..3
    const int warp_m = wid >> 1;     // 0..3 -> m rows 32*warp_m
    const int warp_n = wid & 1;      // 0..1 -> n cols 32*warp_n
    const int s0 = blockIdx.x * MT;
    const int h0 = blockIdx.y * NT;

    auto load_chunk = [&](int c, int buf) {
        const __nv_bfloat16* As = &g_a3[(size_t)s0 * KSPLIT + c * KCH];
        unsigned dA = sb + buf * SA_BYTES;
#pragma unroll
        for (int l = 0; l < 4; l++) {
            int f = tid + l * 256;                 // 0..1023
            int r = f >> 3, sg = f & 7;
            cp16(dA + r * (APIT * 2) + sg * 16,
                 As + (size_t)r * KSPLIT + sg * 8);
        }
        const __nv_bfloat16* Bs = &g_w1t[(size_t)h0 * KSPLIT + c * KCH];
        unsigned dB = sb + SMB_OFF + buf * SB_BYTES;
#pragma unroll
        for (int l = 0; l < 2; l++) {
            int f = tid + l * 256;                 // 0..511
            int r = f >> 3, sg = f & 7;
            cp16(dB + r * (APIT * 2) + sg * 16,
                 Bs + (size_t)r * KSPLIT + sg * 8);
        }
        CP_COMMIT();
    };

    float acc[2][4][4];
#pragma unroll
    for (int i = 0; i < 2; i++)
#pragma unroll
        for (int j = 0; j < 4; j++)
#pragma unroll
            for (int r = 0; r < 4; r++) acc[i][j][r] = 0.f;

    load_chunk(0, 0);

#pragma unroll 1
    for (int c = 0; c < NCH; c++) {
        CP_WAIT0();
        __syncthreads();
        if (c + 1 < NCH) load_chunk(c + 1, (c + 1) & 1);

        const int buf = c & 1;
        const __nv_bfloat16* A = sm16 + buf * (SA_BYTES / 2);
        const __nv_bfloat16* B = sm16 + (SMB_OFF / 2) + buf * (SB_BYTES / 2);

#pragma unroll
        for (int ks = 0; ks < KCH / 16; ks++) {
            const int kb = ks * 16;
            // A fragments: 2 m-frags of 16 rows
            uint32_t af[2][4];
#pragma unroll
            for (int mf = 0; mf < 2; mf++) {
                const int rb = warp_m * 32 + mf * 16;
                af[mf][0] = *reinterpret_cast<const uint32_t*>(&A[(rb + g)     * APIT + kb + t * 2]);
                af[mf][1] = *reinterpret_cast<const uint32_t*>(&A[(rb + g + 8) * APIT + kb + t * 2]);
                af[mf][2] = *reinterpret_cast<const uint32_t*>(&A[(rb + g)     * APIT + kb + t * 2 + 8]);
                af[mf][3] = *reinterpret_cast<const uint32_t*>(&A[(rb + g + 8) * APIT + kb + t * 2 + 8]);
            }
            // B fragments: 4 n-frags of 8 cols (B stored [n][k] -> contiguous pairs)
            uint32_t bf[4][2];
#pragma unroll
            for (int nf = 0; nf < 4; nf++) {
                const int nr = warp_n * 32 + nf * 8 + g;
                bf[nf][0] = *reinterpret_cast<const uint32_t*>(&B[nr * APIT + kb + t * 2]);
                bf[nf][1] = *reinterpret_cast<const uint32_t*>(&B[nr * APIT + kb + t * 2 + 8]);
            }
#pragma unroll
            for (int mf = 0; mf < 2; mf++)
#pragma unroll
                for (int nf = 0; nf < 4; nf++)
                    mma16816(acc[mf][nf][0], acc[mf][nf][1], acc[mf][nf][2], acc[mf][nf][3],
                             af[mf][0], af[mf][1], af[mf][2], af[mf][3],
                             bf[nf][0], bf[nf][1]);
        }
        __syncthreads();
    }

    // Epilogue: stage D transposed [n][m] (pitch 132, conflict-free), then
    // coalesced float4 writes to g_curT[h][s].
    float* sT = reinterpret_cast<float*>(smem);   // [64][132] = 33792 B
#pragma unroll
    for (int mf = 0; mf < 2; mf++) {
        const int mb = warp_m * 32 + mf * 16;
#pragma unroll
        for (int nf = 0; nf < 4; nf++) {
            const int nb = warp_n * 32 + nf * 8 + t * 2;
            sT[(nb + 0) * 132 + mb + g]     = acc[mf][nf][0];
            sT[(nb + 1) * 132 + mb + g]     = acc[mf][nf][1];
            sT[(nb + 0) * 132 + mb + g + 8] = acc[mf][nf][2];
            sT[(nb + 1) * 132 + mb + g + 8] = acc[mf][nf][3];
        }
    }
    __syncthreads();
#pragma unroll
    for (int l = 0; l < 8; l++) {
        int f    = tid + l * 256;     // 0..2047
        int hrow = f >> 5;            // 0..63
        int seg  = f & 31;            // m f4-seg
        float4 v = *reinterpret_cast<float4*>(&sT[hrow * 132 + seg * 4]);
        *reinterpret_cast<float4*>(
            &g_curT[(size_t)(h0 + hrow) * SEQ + s0 + seg * 4]) = v;
    }
}

// ---------------------------------------------------------------------------
// Kernel 3: warp-window LIF scan (validated R5) + fused output projection.
// ---------------------------------------------------------------------------
__global__ void __launch_bounds__(128, 1)
snn_table_out_kernel(const float* __restrict__ W2, float* __restrict__ out) {
    extern __shared__ float scs[];    // 4 x 4096 floats
    __shared__ unsigned slast;

    const int tid  = threadIdx.x;
    const int lane = tid & 31;
    const int w    = tid >> 5;
    const int hbase = blockIdx.x * 4;

    const float4* src = reinterpret_cast<const float4*>(&g_curT[(size_t)hbase * SEQ]);
#pragma unroll
    for (int l = 0; l < 32; l++)
        reinterpret_cast<float4*>(scs)[tid + l * 128] = src[tid + l * 128];
    __syncthreads();

    const float dinv = exp2f((float)lane * LOG2_INV_D);
    const float d31  = exp2f(-31.0f * LOG2_INV_D);

    const float* row = &scs[w * SEQ];
    float X = 0.f;
    int   o = 0, carry_bnd = 0, carry_o = 0, cnt = 0;

#pragma unroll 1
    for (int win = 0; win < SEQ / 32; win++) {
        float p = row[win * 32 + lane] * dinv;
#pragma unroll
        for (int off = 1; off < 32; off <<= 1) {
            float v = __shfl_up_sync(0xffffffffu, p, off);
            if (lane >= off) p += v;
        }
        const float Q   = p - dinv;
        const float P31 = __shfl_sync(0xffffffffu, p, 31);

        if (carry_bnd) {
            o = carry_o;
            X = (carry_o == 0) ? 0.f : __shfl_sync(0xffffffffu, p, carry_o - 1);
            carry_bnd = 0;
        }
        for (;;) {
            unsigned mask = __ballot_sync(0xffffffffu, (Q >= X) && (lane >= o));
            if (!mask) {
                X = -DECAYF * (d31 * (P31 - X));
                o = 0;
                break;
            }
            int ts = __ffs(mask) - 1;
            cnt++;
            if (ts >= 29) { carry_bnd = 1; carry_o = ts - 29; break; }
            o = ts + 3;
            X = __shfl_sync(0xffffffffu, p, ts + 2);
        }
    }

    if (lane == 0) g_cnt[hbase + w] = (float)cnt;
    __syncthreads();
    __threadfence();
    if (tid == 0) slast = atomicAdd(&g_done, 1u);
    __syncthreads();

    if (slast == 63) {
        __threadfence();
        volatile float* vc = g_cnt;
        float a = 0.f;
#pragma unroll 16
        for (int k = 0; k < HID; k++)
            a += vc[k] * W2[(size_t)k * OUTD + tid];
        a *= (1.0f / (float)SEQ);
#pragma unroll
        for (int b = 0; b < BATCH; b++)
            out[(size_t)b * OUTD + tid] = a;
        __threadfence();
        if (tid == 0) g_done = 0;
    }
}

// ---------------------------------------------------------------------------
extern "C" void kernel_launch(void* const* d_in, const int* in_sizes, int n_in,
                              void* d_out, int out_size) {
    const float* x  = (const float*)d_in[0];   // [32][4096][512]
    const float* w1 = (const float*)d_in[1];   // [512][256]
    const float* w2 = (const float*)d_in[2];   // [256][128]
    float* out = (float*)d_out;                // [32][128]

    cudaFuncSetAttribute(snn_mma_kernel,
                         cudaFuncAttributeMaxDynamicSharedMemorySize,
                         MMA_SMEM_BYTES);
    cudaFuncSetAttribute(snn_table_out_kernel,
                         cudaFuncAttributeMaxDynamicSharedMemorySize,
                         4 * SEQ * (int)sizeof(float));

    snn_wprep_kernel<<<EMBED, HID>>>(w1);
    snn_mean_kernel<<<(SEQ * EMBED / 4 + 255) / 256, 256>>>(x);
    snn_mma_kernel<<<dim3(SEQ / MT, HID / NT), 256, MMA_SMEM_BYTES>>>();
    snn_table_out_kernel<<<HID / 4, 128, 4 * SEQ * sizeof(float)>>>(w2, out);
}

// round 11
// speedup vs baseline: 1.4658x; 1.1181x over previous
#include <cuda_runtime.h>
#include <cuda_bf16.h>
#include <cstdint>

#define BATCH 32
#define SEQ   4096
#define EMBED 512
#define HID   256
#define OUTD  128
#define DECAYF 0.95f
#define LOG2_INV_D 0.07400058144377693f   // log2(1/0.95)

#define KSPLIT (3 * EMBED)                // 1536: A = (hi | hi | lo)

__device__ __nv_bfloat16 g_a3[SEQ * KSPLIT];    // A split   [4096][1536]
__device__ __nv_bfloat16 g_w1t[HID * KSPLIT];   // W1^T split [256][1536]: (hi|lo|hi)
__device__ float    g_curT[HID * SEQ];          // currents TRANSPOSED [256][4096]
__device__ float    g_cnt[HID];
__device__ unsigned g_done;

// ---------------------------------------------------------------------------
// Kernel 1: batch mean (emits split-bf16 A3) + fused W1 split prep.
// Blocks 0..2047: mean. Blocks 2048..2559: wprep (k = bid-2048).
// ---------------------------------------------------------------------------
__global__ void snn_mean_kernel(const float* __restrict__ x,
                                const float* __restrict__ W1) {
    if (blockIdx.x >= 2048) {                 // --- wprep part ---
        const int k = blockIdx.x - 2048;      // 0..511
        const int n = threadIdx.x;            // 0..255
        float v = W1[(size_t)k * HID + n];
        __nv_bfloat16 hi = __float2bfloat16(v);
        __nv_bfloat16 lo = __float2bfloat16(v - __bfloat162float(hi));
        g_w1t[(size_t)n * KSPLIT + k]             = hi;
        g_w1t[(size_t)n * KSPLIT + EMBED + k]     = lo;
        g_w1t[(size_t)n * KSPLIT + 2 * EMBED + k] = hi;
        return;
    }
    const int NF4 = (SEQ * EMBED) / 4;
    int i = blockIdx.x * blockDim.x + threadIdx.x;
    if (i >= NF4) return;
    const float4* x4 = reinterpret_cast<const float4*>(x);
    float sx = 0.f, sy = 0.f, sz = 0.f, sw = 0.f;
#pragma unroll
    for (int b = 0; b < BATCH; b++) {
        float4 v = x4[(size_t)b * NF4 + i];
        sx += v.x; sy += v.y; sz += v.z; sw += v.w;
    }
    const float inv = 1.0f / 32.0f;
    float v0 = sx * inv, v1 = sy * inv, v2 = sz * inv, v3 = sw * inv;

    __nv_bfloat16 h0 = __float2bfloat16(v0), h1 = __float2bfloat16(v1);
    __nv_bfloat16 h2 = __float2bfloat16(v2), h3 = __float2bfloat16(v3);
    __nv_bfloat16 l0 = __float2bfloat16(v0 - __bfloat162float(h0));
    __nv_bfloat16 l1 = __float2bfloat16(v1 - __bfloat162float(h1));
    __nv_bfloat16 l2 = __float2bfloat16(v2 - __bfloat162float(h2));
    __nv_bfloat16 l3 = __float2bfloat16(v3 - __bfloat162float(h3));

    __nv_bfloat162 ha = {h0, h1}, hb = {h2, h3};
    __nv_bfloat162 la = {l0, l1}, lb = {l2, l3};
    uint2 hu, lu;
    hu.x = *reinterpret_cast<unsigned*>(&ha); hu.y = *reinterpret_cast<unsigned*>(&hb);
    lu.x = *reinterpret_cast<unsigned*>(&la); lu.y = *reinterpret_cast<unsigned*>(&lb);

    const int s = i >> 7, d4 = i & 127;
    const size_t base = (size_t)s * KSPLIT + d4 * 4;
    *reinterpret_cast<uint2*>(&g_a3[base])             = hu;
    *reinterpret_cast<uint2*>(&g_a3[base + EMBED])     = hu;
    *reinterpret_cast<uint2*>(&g_a3[base + 2 * EMBED]) = lu;
}

// ---------------------------------------------------------------------------
// Kernel 2: HMMA bf16 GEMM via mma.sync.m16n8k16 (R10-validated), with the
// cp.async pipeline fixed to keep one group in flight (wait_group 1).
// ---------------------------------------------------------------------------
#define MT 128
#define NT 64
#define KCH 64
#define NCH (KSPLIT / KCH)        // 24
#define APIT 72
#define SA_BYTES (MT * APIT * 2)  // 18432
#define SB_BYTES (NT * APIT * 2)  // 9216
#define SMB_OFF 36864
#define MMA_SMEM_BYTES 55296

__device__ __forceinline__ void cp16(unsigned dst, const void* src) {
    asm volatile("cp.async.cg.shared.global [%0], [%1], 16;" :: "r"(dst), "l"(src));
}
#define CP_COMMIT() asm volatile("cp.async.commit_group;")
#define CP_WAIT1()  asm volatile("cp.async.wait_group 1;")
#define CP_WAIT0()  asm volatile("cp.async.wait_group 0;")

__device__ __forceinline__ void mma16816(float& d0, float& d1, float& d2, float& d3,
                                         uint32_t a0, uint32_t a1, uint32_t a2, uint32_t a3,
                                         uint32_t b0, uint32_t b1) {
    asm volatile(
        "mma.sync.aligned.m16n8k16.row.col.f32.bf16.bf16.f32 "
        "{%0,%1,%2,%3}, {%4,%5,%6,%7}, {%8,%9}, {%0,%1,%2,%3};"
        : "+f"(d0), "+f"(d1), "+f"(d2), "+f"(d3)
        : "r"(a0), "r"(a1), "r"(a2), "r"(a3), "r"(b0), "r"(b1));
}

__global__ void __launch_bounds__(256, 1)
snn_mma_kernel(void) {
    extern __shared__ char smem[];
    const unsigned sb = (unsigned)__cvta_generic_to_shared(smem);
    __nv_bfloat16* sm16 = reinterpret_cast<__nv_bfloat16*>(smem);

    const int tid  = threadIdx.x;
    const int wid  = tid >> 5;
    const int lane = tid & 31;
    const int g = lane >> 2;
    const int t = lane & 3;
    const int warp_m = wid >> 1;
    const int warp_n = wid & 1;
    const int s0 = blockIdx.x * MT;
    const int h0 = blockIdx.y * NT;

    auto load_chunk = [&](int c, int buf) {
        const __nv_bfloat16* As = &g_a3[(size_t)s0 * KSPLIT + c * KCH];
        unsigned dA = sb + buf * SA_BYTES;
#pragma unroll
        for (int l = 0; l < 4; l++) {
            int f = tid + l * 256;
            int r = f >> 3, sg = f & 7;
            cp16(dA + r * (APIT * 2) + sg * 16, As + (size_t)r * KSPLIT + sg * 8);
        }
        const __nv_bfloat16* Bs = &g_w1t[(size_t)h0 * KSPLIT + c * KCH];
        unsigned dB = sb + SMB_OFF + buf * SB_BYTES;
#pragma unroll
        for (int l = 0; l < 2; l++) {
            int f = tid + l * 256;
            int r = f >> 3, sg = f & 7;
            cp16(dB + r * (APIT * 2) + sg * 16, Bs + (size_t)r * KSPLIT + sg * 8);
        }
        CP_COMMIT();
    };

    float acc[2][4][4];
#pragma unroll
    for (int i = 0; i < 2; i++)
#pragma unroll
        for (int j = 0; j < 4; j++)
#pragma unroll
            for (int r = 0; r < 4; r++) acc[i][j][r] = 0.f;

    load_chunk(0, 0);
    load_chunk(1, 1);

#pragma unroll 1
    for (int c = 0; c < NCH; c++) {
        if (c + 1 < NCH) CP_WAIT1(); else CP_WAIT0();
        __syncthreads();

        const int buf = c & 1;
        const __nv_bfloat16* A = sm16 + buf * (SA_BYTES / 2);
        const __nv_bfloat16* B = sm16 + (SMB_OFF / 2) + buf * (SB_BYTES / 2);

#pragma unroll
        for (int ks = 0; ks < KCH / 16; ks++) {
            const int kb = ks * 16;
            uint32_t af[2][4];
#pragma unroll
            for (int mf = 0; mf < 2; mf++) {
                const int rb = warp_m * 32 + mf * 16;
                af[mf][0] = *reinterpret_cast<const uint32_t*>(&A[(rb + g)     * APIT + kb + t * 2]);
                af[mf][1] = *reinterpret_cast<const uint32_t*>(&A[(rb + g + 8) * APIT + kb + t * 2]);
                af[mf][2] = *reinterpret_cast<const uint32_t*>(&A[(rb + g)     * APIT + kb + t * 2 + 8]);
                af[mf][3] = *reinterpret_cast<const uint32_t*>(&A[(rb + g + 8) * APIT + kb + t * 2 + 8]);
            }
            uint32_t bf[4][2];
#pragma unroll
            for (int nf = 0; nf < 4; nf++) {
                const int nr = warp_n * 32 + nf * 8 + g;
                bf[nf][0] = *reinterpret_cast<const uint32_t*>(&B[nr * APIT + kb + t * 2]);
                bf[nf][1] = *reinterpret_cast<const uint32_t*>(&B[nr * APIT + kb + t * 2 + 8]);
            }
#pragma unroll
            for (int mf = 0; mf < 2; mf++)
#pragma unroll
                for (int nf = 0; nf < 4; nf++)
                    mma16816(acc[mf][nf][0], acc[mf][nf][1], acc[mf][nf][2], acc[mf][nf][3],
                             af[mf][0], af[mf][1], af[mf][2], af[mf][3],
                             bf[nf][0], bf[nf][1]);
        }
        __syncthreads();
        if (c + 2 < NCH) load_chunk(c + 2, buf);
    }

    float* sT = reinterpret_cast<float*>(smem);   // [64][132]
#pragma unroll
    for (int mf = 0; mf < 2; mf++) {
        const int mb = warp_m * 32 + mf * 16;
#pragma unroll
        for (int nf = 0; nf < 4; nf++) {
            const int nb = warp_n * 32 + nf * 8 + t * 2;
            sT[(nb + 0) * 132 + mb + g]     = acc[mf][nf][0];
            sT[(nb + 1) * 132 + mb + g]     = acc[mf][nf][1];
            sT[(nb + 0) * 132 + mb + g + 8] = acc[mf][nf][2];
            sT[(nb + 1) * 132 + mb + g + 8] = acc[mf][nf][3];
        }
    }
    __syncthreads();
#pragma unroll
    for (int l = 0; l < 8; l++) {
        int f    = tid + l * 256;
        int hrow = f >> 5;
        int seg  = f & 31;
        float4 v = *reinterpret_cast<float4*>(&sT[hrow * 132 + seg * 4]);
        *reinterpret_cast<float4*>(
            &g_curT[(size_t)(h0 + hrow) * SEQ + s0 + seg * 4]) = v;
    }
}

// ---------------------------------------------------------------------------
// Kernel 3: two-phase LIF scan. One block per unit, 256 threads.
// Phase A (8 warps x 16 windows, parallel): per window build P/Q prefix,
//   skip-max table M_k, next-spike N(r) for every restart lane r (5-level
//   descent), then 4 rounds of pointer doubling -> T(r) = {count, terminal}.
//   Terminal: CARRY(o in 0..2) into next window, or LAST_RESTART(r_f).
// Phase B (warp 0, serial over 128 windows): entry state is CARRY(o) or
//   CONT(X); CARRY -> one shfl lookup of T(o); CONT -> one ballot for the
//   first spike, then one shfl lookup. Same algebra as the validated R5 scan.
// Fused output projection in the last finishing block.
// T packing: {count:bits7+, term:bits5-6 (0=chain,1=CARRY,2=LASTR), pos:bits0-4}
// ---------------------------------------------------------------------------
// dynamic smem floats: sQ @0 [4096], sXR @4096 [4096], sTT @8192 [4096], sP31 @12288 [128]
#define SCAN_SMEM_FLOATS (3 * SEQ + 128)
#define SCAN_SMEM_BYTES  (SCAN_SMEM_FLOATS * 4)
#define FULLW 0xffffffffu

__global__ void __launch_bounds__(256, 1)
snn_scan_kernel(const float* __restrict__ W2, float* __restrict__ out) {
    extern __shared__ float ssm[];
    float*    sQ   = ssm;
    float*    sXR  = ssm + SEQ;
    unsigned* sTT  = reinterpret_cast<unsigned*>(ssm + 2 * SEQ);
    float*    sP31 = ssm + 3 * SEQ;
    __shared__ unsigned slast;

    const int h    = blockIdx.x;
    const int tid  = threadIdx.x;
    const int lane = tid & 31;
    const int warp = tid >> 5;

    const float dinv = exp2f((float)lane * LOG2_INV_D);   // d^{-lane}
    const float d31  = exp2f(-31.0f * LOG2_INV_D);        // d^31

    // ===== Phase A =====
#pragma unroll 1
    for (int win = warp; win < SEQ / 32; win += 8) {
        float c = g_curT[(size_t)h * SEQ + win * 32 + lane];
        float p = c * dinv;
#pragma unroll
        for (int off = 1; off < 32; off <<= 1) {
            float v = __shfl_up_sync(FULLW, p, off);
            if (lane >= off) p += v;
        }
        float Q  = p - dinv;
        float pv = __shfl_up_sync(FULLW, p, 1);
        float XR = (lane == 0) ? 0.f : pv;                // P_{lane-1}

        // skip-max table: M_k[t] = max Q over [t, min(t+2^k-1, 31)]
        float M0 = Q;
        float M1 = fmaxf(M0, __shfl_down_sync(FULLW, M0, 1));
        float M2 = fmaxf(M1, __shfl_down_sync(FULLW, M1, 2));
        float M3 = fmaxf(M2, __shfl_down_sync(FULLW, M2, 4));
        float M4 = fmaxf(M3, __shfl_down_sync(FULLW, M3, 8));
        float M5 = fmaxf(M4, __shfl_down_sync(FULLW, M4, 16)); // suffix max

        // N(r): first u >= r with Q_u >= XR  (descent over M tables)
        const float X = XR;
        const bool exists = (M5 >= X);
        int pos = lane;
        {
            float mk;
            mk = __shfl_sync(FULLW, M4, pos & 31); if (mk < X) pos += 16;
            mk = __shfl_sync(FULLW, M3, pos & 31); if (mk < X) pos += 8;
            mk = __shfl_sync(FULLW, M2, pos & 31); if (mk < X) pos += 4;
            mk = __shfl_sync(FULLW, M1, pos & 31); if (mk < X) pos += 2;
            mk = __shfl_sync(FULLW, M0, pos & 31); if (mk < X) pos += 1;
        }
        // initial doubling state
        unsigned st;
        if (!exists)         st = (2u << 5) | (unsigned)lane;          // LASTR(r), cnt 0
        else if (pos <= 28)  st = (1u << 7) | (0u << 5) | (unsigned)(pos + 3);
        else                 st = (1u << 7) | (1u << 5) | (unsigned)(pos - 29);

        // 4 rounds of pointer doubling (max 11 restarts per window)
#pragma unroll
        for (int r = 0; r < 4; r++) {
            unsigned s2 = __shfl_sync(FULLW, st, st & 31);
            if (((st >> 5) & 3u) == 0u)
                st = (((st >> 7) + (s2 >> 7)) << 7) | (s2 & 0x7Fu);
        }

        sQ [win * 32 + lane] = Q;
        sXR[win * 32 + lane] = XR;
        sTT[win * 32 + lane] = st;
        if (lane == 31) sP31[win] = p;
    }
    __syncthreads();

    // ===== Phase B (warp 0) =====
    if (warp == 0) {
        int   isCarry = 1, o = 0, cnt = 0;
        float X = 0.f;
#pragma unroll 1
        for (int win = 0; win < SEQ / 32; win++) {
            float    Qv  = sQ [win * 32 + lane];
            float    XRv = sXR[win * 32 + lane];
            unsigned Tv  = sTT[win * 32 + lane];
            float    P31 = sP31[win];

            unsigned st;
            if (isCarry) {
                st = __shfl_sync(FULLW, Tv, o);
            } else {
                unsigned ball = __ballot_sync(FULLW, Qv >= X);
                if (!ball) { X = -DECAYF * (d31 * (P31 - X)); continue; }
                int t1 = __ffs(ball) - 1;
                cnt++;
                if (t1 >= 29) { isCarry = 1; o = t1 - 29; continue; }
                st = __shfl_sync(FULLW, Tv, t1 + 3);
            }
            cnt += (int)(st >> 7);
            unsigned term = (st >> 5) & 3u;
            unsigned p5   = st & 31u;
            float xr = __shfl_sync(FULLW, XRv, p5);
            if (term == 1u) { isCarry = 1; o = (int)p5; }
            else            { isCarry = 0; X = -DECAYF * (d31 * (P31 - xr)); }
        }
        if (lane == 0) g_cnt[h] = (float)cnt;
    }
    __syncthreads();
    __threadfence();
    if (tid == 0) slast = atomicAdd(&g_done, 1u);
    __syncthreads();

    if (slast == HID - 1 && tid < OUTD) {
        __threadfence();
        volatile float* vc = g_cnt;
        float a = 0.f;
#pragma unroll 16
        for (int k = 0; k < HID; k++)
            a += vc[k] * W2[(size_t)k * OUTD + tid];
        a *= (1.0f / (float)SEQ);
#pragma unroll
        for (int b = 0; b < BATCH; b++)
            out[(size_t)b * OUTD + tid] = a;
        __threadfence();
        if (tid == 0) g_done = 0;
    }
}

// ---------------------------------------------------------------------------
extern "C" void kernel_launch(void* const* d_in, const int* in_sizes, int n_in,
                              void* d_out, int out_size) {
    const float* x  = (const float*)d_in[0];   // [32][4096][512]
    const float* w1 = (const float*)d_in[1];   // [512][256]
    const float* w2 = (const float*)d_in[2];   // [256][128]
    float* out = (float*)d_out;                // [32][128]

    cudaFuncSetAttribute(snn_mma_kernel,
                         cudaFuncAttributeMaxDynamicSharedMemorySize,
                         MMA_SMEM_BYTES);
    cudaFuncSetAttribute(snn_scan_kernel,
                         cudaFuncAttributeMaxDynamicSharedMemorySize,
                         SCAN_SMEM_BYTES);

    snn_mean_kernel<<<2048 + EMBED, 256>>>(x, w1);
    snn_mma_kernel<<<dim3(SEQ / MT, HID / NT), 256, MMA_SMEM_BYTES>>>();
    snn_scan_kernel<<<HID, 256, SCAN_SMEM_BYTES>>>(w2, out);
}